// round 1
// baseline (speedup 1.0000x reference)
#include <cuda_runtime.h>
#include <cstddef>

#define L_NODES 100000
#define NFEAT   256
#define JDIM    128
#define SSAMP   8

// ---------------- scratch (static __device__ — no allocations allowed) -----
__device__ float g_H[(size_t)L_NODES * JDIM];        //  51.2 MB  H = relu(X@Wh1+b)
__device__ float g_AB[(size_t)L_NODES * 2 * JDIM];   // 102.4 MB  [A|B] = H@[Wtop|Wbot]
__device__ float g_E[(size_t)L_NODES * JDIM];        //  51.2 MB  E after gather/mean
__device__ float g_C[(size_t)L_NODES * JDIM];        //  51.2 MB  C = E@Wbot
__device__ float g_Wcat[JDIM * 2 * JDIM];            //  [Wtop|Wbot] side-by-side (128x256)

// ---------------- generic 128x128x8 register-blocked SGEMM -----------------
// C(MxN, stride N) = A(MxK, stride K) * B(KxN, stride ldb) [+bias][relu]
__global__ __launch_bounds__(256) void sgemm128(
    const float* __restrict__ A, const float* __restrict__ B,
    float* __restrict__ C, const float* __restrict__ bias,
    int M, int K, int N, int ldb, int do_relu)
{
    __shared__ float As[8][128];   // transposed A tile: As[k][m]
    __shared__ float Bs[8][128];

    const int tid  = threadIdx.x;
    const int bm   = blockIdx.x;
    const int colN = blockIdx.y * 128;
    const int tx   = tid & 15;
    const int ty   = tid >> 4;
    const int rowBase = ty * 8;
    const int colBase = tx * 8;
    const int aRow = tid >> 1;
    const int aCol = (tid & 1) * 4;
    const int bRow = tid >> 5;
    const int bCol = (tid & 31) * 4;
    const int gRowA = bm * 128 + aRow;

    float acc[8][8];
#pragma unroll
    for (int i = 0; i < 8; ++i)
#pragma unroll
        for (int j = 0; j < 8; ++j) acc[i][j] = 0.f;

    const int ktiles = K >> 3;
    for (int kt = 0; kt < ktiles; ++kt) {
        float4 a4 = make_float4(0.f, 0.f, 0.f, 0.f);
        if (gRowA < M)
            a4 = *(const float4*)&A[(size_t)gRowA * K + (kt << 3) + aCol];
        As[aCol + 0][aRow] = a4.x;
        As[aCol + 1][aRow] = a4.y;
        As[aCol + 2][aRow] = a4.z;
        As[aCol + 3][aRow] = a4.w;
        *(float4*)&Bs[bRow][bCol] =
            *(const float4*)&B[(size_t)((kt << 3) + bRow) * ldb + colN + bCol];
        __syncthreads();
#pragma unroll
        for (int k = 0; k < 8; ++k) {
            float ar[8], br[8];
            *(float4*)&ar[0] = *(const float4*)&As[k][rowBase];
            *(float4*)&ar[4] = *(const float4*)&As[k][rowBase + 4];
            *(float4*)&br[0] = *(const float4*)&Bs[k][colBase];
            *(float4*)&br[4] = *(const float4*)&Bs[k][colBase + 4];
#pragma unroll
            for (int i = 0; i < 8; ++i)
#pragma unroll
                for (int j = 0; j < 8; ++j)
                    acc[i][j] += ar[i] * br[j];
        }
        __syncthreads();
    }

    float bv[8];
#pragma unroll
    for (int j = 0; j < 8; ++j)
        bv[j] = bias ? bias[colN + colBase + j] : 0.f;

#pragma unroll
    for (int i = 0; i < 8; ++i) {
        const int row = bm * 128 + rowBase + i;
        if (row < M) {
            float tmp[8];
#pragma unroll
            for (int j = 0; j < 8; ++j) {
                float v = acc[i][j] + bv[j];
                tmp[j] = do_relu ? fmaxf(v, 0.f) : v;
            }
            *(float4*)&C[(size_t)row * N + colN + colBase]     = *(float4*)&tmp[0];
            *(float4*)&C[(size_t)row * N + colN + colBase + 4] = *(float4*)&tmp[4];
        }
    }
}

// ---------------- build [Wtop | Wbot] (128 x 256) from W_g1 (256 x 128) ----
__global__ void build_wcat(const float* __restrict__ Wg)
{
    int i = blockIdx.x * blockDim.x + threadIdx.x;   // 0..32767
    if (i >= JDIM * 2 * JDIM) return;
    int k = i >> 8;         // row in Wcat (0..127)
    int n = i & 255;        // col in Wcat (0..255)
    g_Wcat[i] = (n < JDIM) ? Wg[k * JDIM + n]
                           : Wg[(JDIM + k) * JDIM + (n - JDIM)];
}

// ---------------- E[l] = relu( mean_s relu(A[idx0]+B[idx1]+b_g1) ) ---------
// one warp per node; each lane owns 4 contiguous features (float4)
__global__ __launch_bounds__(256) void gather_mean(
    const int* __restrict__ idx0, const int* __restrict__ idx1,
    const float* __restrict__ bg)
{
    const int warp = (blockIdx.x * blockDim.x + threadIdx.x) >> 5;
    const int lane = threadIdx.x & 31;
    if (warp >= L_NODES) return;
    const int c = lane * 4;
    const float b0 = bg[c], b1 = bg[c + 1], b2 = bg[c + 2], b3 = bg[c + 3];
    float4 acc = make_float4(0.f, 0.f, 0.f, 0.f);
#pragma unroll
    for (int s = 0; s < SSAMP; ++s) {
        const int i0 = idx0[s * L_NODES + warp];
        const int i1 = idx1[s * L_NODES + warp];
        const float4 a  = *(const float4*)&g_AB[(size_t)i0 * 256 + c];
        const float4 bb = *(const float4*)&g_AB[(size_t)i1 * 256 + 128 + c];
        acc.x += fmaxf(a.x + bb.x + b0, 0.f);
        acc.y += fmaxf(a.y + bb.y + b1, 0.f);
        acc.z += fmaxf(a.z + bb.z + b2, 0.f);
        acc.w += fmaxf(a.w + bb.w + b3, 0.f);
    }
    const float inv = 1.f / (float)SSAMP;
    float4 e;
    e.x = fmaxf(acc.x * inv, 0.f);
    e.y = fmaxf(acc.y * inv, 0.f);
    e.z = fmaxf(acc.z * inv, 0.f);
    e.w = fmaxf(acc.w * inv, 0.f);
    *(float4*)&g_E[(size_t)warp * JDIM + c] = e;
}

// ---------------- out = relu(A + C + b_g1) @ W_f + b_f ---------------------
// one warp per node; warp-reduce the two output dots
__global__ __launch_bounds__(256) void final_out(
    const float* __restrict__ bg, const float* __restrict__ Wf,
    const float* __restrict__ bf, float* __restrict__ out)
{
    const int warp = (blockIdx.x * blockDim.x + threadIdx.x) >> 5;
    const int lane = threadIdx.x & 31;
    if (warp >= L_NODES) return;
    const int c = lane * 4;
    const float4 a  = *(const float4*)&g_AB[(size_t)warp * 256 + c];  // A = H@Wtop
    const float4 cc = *(const float4*)&g_C[(size_t)warp * JDIM + c];  // C = E@Wbot
    const float av[4] = {a.x, a.y, a.z, a.w};
    const float cv[4] = {cc.x, cc.y, cc.z, cc.w};
    float s0 = 0.f, s1 = 0.f;
#pragma unroll
    for (int j = 0; j < 4; ++j) {
        const float e = fmaxf(av[j] + cv[j] + bg[c + j], 0.f);
        s0 += e * Wf[(c + j) * 2 + 0];
        s1 += e * Wf[(c + j) * 2 + 1];
    }
#pragma unroll
    for (int off = 16; off; off >>= 1) {
        s0 += __shfl_xor_sync(0xffffffffu, s0, off);
        s1 += __shfl_xor_sync(0xffffffffu, s1, off);
    }
    if (lane == 0) {
        out[(size_t)warp * 2 + 0] = s0 + bf[0];
        out[(size_t)warp * 2 + 1] = s1 + bf[1];
    }
}

// ---------------------------------------------------------------------------
extern "C" void kernel_launch(void* const* d_in, const int* in_sizes, int n_in,
                              void* d_out, int out_size)
{
    const float* X    = (const float*)d_in[0];
    const float* Wh1  = (const float*)d_in[1];
    const float* bh1  = (const float*)d_in[2];
    const float* Wg1  = (const float*)d_in[3];
    const float* bg1  = (const float*)d_in[4];
    const float* Wf   = (const float*)d_in[5];
    const float* bf   = (const float*)d_in[6];
    const int*   idx0 = (const int*)d_in[7];
    const int*   idx1 = (const int*)d_in[8];
    float* out = (float*)d_out;

    float *H, *AB, *E, *C, *Wcat;
    cudaGetSymbolAddress((void**)&H,    g_H);
    cudaGetSymbolAddress((void**)&AB,   g_AB);
    cudaGetSymbolAddress((void**)&E,    g_E);
    cudaGetSymbolAddress((void**)&C,    g_C);
    cudaGetSymbolAddress((void**)&Wcat, g_Wcat);

    const int mtiles = (L_NODES + 127) / 128;   // 782
    dim3 blk(256);

    // Wcat build (independent of H gemm, ordered on stream anyway)
    build_wcat<<<(JDIM * 2 * JDIM + 255) / 256, 256>>>(Wg1);

    // 1) H = relu(X @ Wh1 + bh1)                (1e5,256)@(256,128)
    sgemm128<<<dim3(mtiles, 1), blk>>>(X, Wh1, H, bh1, L_NODES, NFEAT, JDIM, JDIM, 1);

    // 2) [A|B] = H @ [Wtop|Wbot]                (1e5,128)@(128,256)
    sgemm128<<<dim3(mtiles, 2), blk>>>(H, Wcat, AB, nullptr, L_NODES, JDIM, 2 * JDIM, 2 * JDIM, 0);

    // 3) E = relu(mean_s relu(A[idx0]+B[idx1]+b_g1))
    gather_mean<<<(L_NODES + 7) / 8, 256>>>(idx0, idx1, bg1);

    // 4) C = E @ Wbot                           (1e5,128)@(128,128)
    sgemm128<<<dim3(mtiles, 1), blk>>>(E, Wg1 + JDIM * JDIM, C, nullptr, L_NODES, JDIM, JDIM, JDIM, 0);

    // 5) out = relu(A + C + b_g1) @ Wf + bf
    final_out<<<(L_NODES + 7) / 8, 256>>>(bg1, Wf, bf, out);
}

// round 2
// speedup vs baseline: 1.6668x; 1.6668x over previous
#include <cuda_runtime.h>
#include <mma.h>
#include <cstddef>

using namespace nvcuda;

#define L_NODES 100000
#define NFEAT   256
#define JDIM    128
#define SSAMP   8

// ---------------- scratch (static __device__ — no allocations allowed) -----
__device__ float g_H[(size_t)L_NODES * JDIM];        //  51.2 MB
__device__ float g_AB[(size_t)L_NODES * 2 * JDIM];   // 102.4 MB  [A|B]
__device__ float g_E[(size_t)L_NODES * JDIM];        //  51.2 MB
__device__ float g_C[(size_t)L_NODES * JDIM];        //  51.2 MB
__device__ float g_Wcat[JDIM * 2 * JDIM];            //  [Wtop|Wbot] (128x256)

// ---------------- tf32 wmma GEMM: C = op(A@B + bias) -----------------------
// A: MxK row-major (lda=K). B: KxN-slice row-major (ldb given). C: MxN (ldc=N).
// Block tile 128x128, 8 warps (2x4), warp tile 64x32, K-chunk 32.
#define AS_LD 36      // 32 + 4 pad, float4-aligned (36*4B = 144B, 16B mult)
#define BS_LD 132     // 128 + 4 pad (528B, 16B mult)
#define CS_LD 132

extern __shared__ float smem_dyn[];

__global__ __launch_bounds__(256) void gemm_tf32(
    const float* __restrict__ A, const float* __restrict__ B,
    float* __restrict__ C, const float* __restrict__ bias,
    int M, int K, int N, int ldb, int do_relu)
{
    float* As = smem_dyn;                 // 128 x AS_LD
    float* Bs = smem_dyn + 128 * AS_LD;   // 32 x BS_LD
    float* Cs = smem_dyn;                 // reused after k-loop: 128 x CS_LD

    const int tid    = threadIdx.x;
    const int warpId = tid >> 5;
    const int wRow   = warpId >> 2;       // 0..1  -> 64 rows each
    const int wCol   = warpId & 3;        // 0..3  -> 32 cols each
    const int bm     = blockIdx.x;
    const int colN   = blockIdx.y * 128;
    const int rowN   = bm * 128;

    wmma::fragment<wmma::accumulator, 16, 16, 8, float> c[4][2];
#pragma unroll
    for (int mi = 0; mi < 4; ++mi)
#pragma unroll
        for (int ni = 0; ni < 2; ++ni) wmma::fill_fragment(c[mi][ni], 0.f);

    const int ktiles = K >> 5;  // K-chunks of 32
    for (int kt = 0; kt < ktiles; ++kt) {
        // load A chunk: 128 rows x 32 cols  (1024 float4, 4 per thread)
#pragma unroll
        for (int it = 0; it < 4; ++it) {
            const int i   = tid + it * 256;
            const int r   = i >> 3;            // 0..127
            const int c4  = i & 7;             // 0..7 (x4 floats)
            const int gr  = rowN + r;
            float4 v = make_float4(0.f, 0.f, 0.f, 0.f);
            if (gr < M)
                v = *(const float4*)&A[(size_t)gr * K + (kt << 5) + c4 * 4];
            *(float4*)&As[r * AS_LD + c4 * 4] = v;
        }
        // load B chunk: 32 rows x 128 cols
#pragma unroll
        for (int it = 0; it < 4; ++it) {
            const int i  = tid + it * 256;
            const int r  = i >> 5;             // 0..31
            const int c4 = i & 31;             // 0..31 (x4 floats)
            *(float4*)&Bs[r * BS_LD + c4 * 4] =
                *(const float4*)&B[(size_t)((kt << 5) + r) * ldb + colN + c4 * 4];
        }
        __syncthreads();

#pragma unroll
        for (int ks = 0; ks < 4; ++ks) {
            wmma::fragment<wmma::matrix_a, 16, 16, 8, wmma::precision::tf32, wmma::row_major> a[4];
            wmma::fragment<wmma::matrix_b, 16, 16, 8, wmma::precision::tf32, wmma::row_major> b[2];
#pragma unroll
            for (int mi = 0; mi < 4; ++mi) {
                wmma::load_matrix_sync(a[mi], &As[(wRow * 64 + mi * 16) * AS_LD + ks * 8], AS_LD);
#pragma unroll
                for (int t = 0; t < a[mi].num_elements; ++t)
                    a[mi].x[t] = wmma::__float_to_tf32(a[mi].x[t]);
            }
#pragma unroll
            for (int ni = 0; ni < 2; ++ni) {
                wmma::load_matrix_sync(b[ni], &Bs[(ks * 8) * BS_LD + wCol * 32 + ni * 16], BS_LD);
#pragma unroll
                for (int t = 0; t < b[ni].num_elements; ++t)
                    b[ni].x[t] = wmma::__float_to_tf32(b[ni].x[t]);
            }
#pragma unroll
            for (int mi = 0; mi < 4; ++mi)
#pragma unroll
                for (int ni = 0; ni < 2; ++ni)
                    wmma::mma_sync(c[mi][ni], a[mi], b[ni], c[mi][ni]);
        }
        __syncthreads();
    }

    // epilogue: stage to smem, then fused bias+relu vectorized global store
#pragma unroll
    for (int mi = 0; mi < 4; ++mi)
#pragma unroll
        for (int ni = 0; ni < 2; ++ni)
            wmma::store_matrix_sync(
                &Cs[(wRow * 64 + mi * 16) * CS_LD + wCol * 32 + ni * 16],
                c[mi][ni], CS_LD, wmma::mem_row_major);
    __syncthreads();

#pragma unroll
    for (int it = 0; it < 16; ++it) {
        const int i  = tid + it * 256;
        const int r  = i >> 5;
        const int c4 = i & 31;
        const int gr = rowN + r;
        if (gr < M) {
            float4 v = *(float4*)&Cs[r * CS_LD + c4 * 4];
            if (bias) {
                v.x += bias[colN + c4 * 4 + 0];
                v.y += bias[colN + c4 * 4 + 1];
                v.z += bias[colN + c4 * 4 + 2];
                v.w += bias[colN + c4 * 4 + 3];
            }
            if (do_relu) {
                v.x = fmaxf(v.x, 0.f); v.y = fmaxf(v.y, 0.f);
                v.z = fmaxf(v.z, 0.f); v.w = fmaxf(v.w, 0.f);
            }
            *(float4*)&C[(size_t)gr * N + colN + c4 * 4] = v;
        }
    }
}

#define GEMM_SMEM_BYTES (128 * CS_LD * 4)   // 67584 B (covers As+Bs too)

// ---------------- build [Wtop | Wbot] (128 x 256) from W_g1 (256 x 128) ----
__global__ void build_wcat(const float* __restrict__ Wg)
{
    int i = blockIdx.x * blockDim.x + threadIdx.x;
    if (i >= JDIM * 2 * JDIM) return;
    int k = i >> 8;
    int n = i & 255;
    g_Wcat[i] = (n < JDIM) ? Wg[k * JDIM + n]
                           : Wg[(JDIM + k) * JDIM + (n - JDIM)];
}

// ---------------- E[l] = relu( mean_s relu(A[idx0]+B[idx1]+b_g1) ) ---------
__global__ __launch_bounds__(256) void gather_mean(
    const int* __restrict__ idx0, const int* __restrict__ idx1,
    const float* __restrict__ bg)
{
    const int warp = (blockIdx.x * blockDim.x + threadIdx.x) >> 5;
    const int lane = threadIdx.x & 31;
    if (warp >= L_NODES) return;
    const int c = lane * 4;
    const float b0 = bg[c], b1 = bg[c + 1], b2 = bg[c + 2], b3 = bg[c + 3];
    float4 acc = make_float4(0.f, 0.f, 0.f, 0.f);
#pragma unroll
    for (int s = 0; s < SSAMP; ++s) {
        const int i0 = idx0[s * L_NODES + warp];
        const int i1 = idx1[s * L_NODES + warp];
        const float4 a  = *(const float4*)&g_AB[(size_t)i0 * 256 + c];
        const float4 bb = *(const float4*)&g_AB[(size_t)i1 * 256 + 128 + c];
        acc.x += fmaxf(a.x + bb.x + b0, 0.f);
        acc.y += fmaxf(a.y + bb.y + b1, 0.f);
        acc.z += fmaxf(a.z + bb.z + b2, 0.f);
        acc.w += fmaxf(a.w + bb.w + b3, 0.f);
    }
    const float inv = 1.f / (float)SSAMP;
    float4 e;
    e.x = fmaxf(acc.x * inv, 0.f);
    e.y = fmaxf(acc.y * inv, 0.f);
    e.z = fmaxf(acc.z * inv, 0.f);
    e.w = fmaxf(acc.w * inv, 0.f);
    *(float4*)&g_E[(size_t)warp * JDIM + c] = e;
}

// ---------------- out = relu(A + C + b_g1) @ W_f + b_f ---------------------
__global__ __launch_bounds__(256) void final_out(
    const float* __restrict__ bg, const float* __restrict__ Wf,
    const float* __restrict__ bf, float* __restrict__ out)
{
    const int warp = (blockIdx.x * blockDim.x + threadIdx.x) >> 5;
    const int lane = threadIdx.x & 31;
    if (warp >= L_NODES) return;
    const int c = lane * 4;
    const float4 a  = *(const float4*)&g_AB[(size_t)warp * 256 + c];
    const float4 cc = *(const float4*)&g_C[(size_t)warp * JDIM + c];
    const float av[4] = {a.x, a.y, a.z, a.w};
    const float cv[4] = {cc.x, cc.y, cc.z, cc.w};
    float s0 = 0.f, s1 = 0.f;
#pragma unroll
    for (int j = 0; j < 4; ++j) {
        const float e = fmaxf(av[j] + cv[j] + bg[c + j], 0.f);
        s0 += e * Wf[(c + j) * 2 + 0];
        s1 += e * Wf[(c + j) * 2 + 1];
    }
#pragma unroll
    for (int off = 16; off; off >>= 1) {
        s0 += __shfl_xor_sync(0xffffffffu, s0, off);
        s1 += __shfl_xor_sync(0xffffffffu, s1, off);
    }
    if (lane == 0) {
        out[(size_t)warp * 2 + 0] = s0 + bf[0];
        out[(size_t)warp * 2 + 1] = s1 + bf[1];
    }
}

// ---------------------------------------------------------------------------
extern "C" void kernel_launch(void* const* d_in, const int* in_sizes, int n_in,
                              void* d_out, int out_size)
{
    const float* X    = (const float*)d_in[0];
    const float* Wh1  = (const float*)d_in[1];
    const float* bh1  = (const float*)d_in[2];
    const float* Wg1  = (const float*)d_in[3];
    const float* bg1  = (const float*)d_in[4];
    const float* Wf   = (const float*)d_in[5];
    const float* bf   = (const float*)d_in[6];
    const int*   idx0 = (const int*)d_in[7];
    const int*   idx1 = (const int*)d_in[8];
    float* out = (float*)d_out;

    float *H, *AB, *E, *C, *Wcat;
    cudaGetSymbolAddress((void**)&H,    g_H);
    cudaGetSymbolAddress((void**)&AB,   g_AB);
    cudaGetSymbolAddress((void**)&E,    g_E);
    cudaGetSymbolAddress((void**)&C,    g_C);
    cudaGetSymbolAddress((void**)&Wcat, g_Wcat);

    cudaFuncSetAttribute(gemm_tf32, cudaFuncAttributeMaxDynamicSharedMemorySize,
                         GEMM_SMEM_BYTES);

    const int mtiles = (L_NODES + 127) / 128;   // 782
    dim3 blk(256);

    build_wcat<<<(JDIM * 2 * JDIM + 255) / 256, 256>>>(Wg1);

    // 1) H = relu(X @ Wh1 + bh1)            (1e5,256)@(256,128)
    gemm_tf32<<<dim3(mtiles, 1), blk, GEMM_SMEM_BYTES>>>(
        X, Wh1, H, bh1, L_NODES, NFEAT, JDIM, JDIM, 1);

    // 2) [A|B] = H @ [Wtop|Wbot]            (1e5,128)@(128,256)
    gemm_tf32<<<dim3(mtiles, 2), blk, GEMM_SMEM_BYTES>>>(
        H, Wcat, AB, nullptr, L_NODES, JDIM, 2 * JDIM, 2 * JDIM, 0);

    // 3) E = relu(mean_s relu(A[idx0]+B[idx1]+b_g1))
    gather_mean<<<(L_NODES + 7) / 8, 256>>>(idx0, idx1, bg1);

    // 4) C = E @ Wbot                       (1e5,128)@(128,128)
    gemm_tf32<<<dim3(mtiles, 1), blk, GEMM_SMEM_BYTES>>>(
        E, Wg1 + JDIM * JDIM, C, nullptr, L_NODES, JDIM, JDIM, JDIM, 0);

    // 5) out = relu(A + C + b_g1) @ Wf + bf
    final_out<<<(L_NODES + 7) / 8, 256>>>(bg1, Wf, bf, out);
}

// round 3
// speedup vs baseline: 1.8059x; 1.0834x over previous
#include <cuda_runtime.h>
#include <mma.h>
#include <cstddef>

using namespace nvcuda;

#define L_NODES 100000
#define NFEAT   256
#define JDIM    128
#define SSAMP   8

// ---------------- scratch (static __device__ — no allocations allowed) -----
__device__ float g_H[(size_t)L_NODES * JDIM];        //  51.2 MB
__device__ float g_AB[(size_t)L_NODES * 2 * JDIM];   // 102.4 MB  [A|B]
__device__ float g_E[(size_t)L_NODES * JDIM];        //  51.2 MB
__device__ float g_Wcat[JDIM * 2 * JDIM];            //  [Wtop|Wbot] (128x256)

// ---------------- smem geometry --------------------------------------------
#define AS_LD 36      // 32 + 4 pad
#define BS_LD 132     // 128 + 4 pad
#define CS_LD 132
// As double buf: 2*128*36 = 9216 floats; Bs double buf: 2*32*132 = 8448
#define SMEM_FLOATS (2 * 128 * AS_LD + 2 * 32 * BS_LD)   // 17664
#define SMEM_BYTES  (SMEM_FLOATS * 4)                     // 70656 (Cs 67584 fits in union)

extern __shared__ float smem_dyn[];

__device__ __forceinline__ float to_tf32(float x)
{
    asm("cvt.rna.tf32.f32 %0, %0;" : "+f"(x));
    return x;
}

// Core: accumulate a 128x128 tile of A(MxK)@B(K x ldb)[colN:colN+128].
// Register-staged double-buffered smem pipeline; tf32 conversion fused into STS.
__device__ __forceinline__ void gemm_tile(
    const float* __restrict__ A, const float* __restrict__ B,
    int M, int K, int ldb, int rowN, int colN, float* smem,
    wmma::fragment<wmma::accumulator, 16, 16, 8, float> (&c)[4][2],
    int wRow, int wCol)
{
    float* AsB[2] = { smem, smem + 128 * AS_LD };
    float* BsB[2] = { smem + 2 * 128 * AS_LD, smem + 2 * 128 * AS_LD + 32 * BS_LD };

    const int tid = threadIdx.x;
    const int aR  = tid >> 3;            // 0..31 base pattern over 4 its -> rows 0..127
    const int aC  = (tid & 7) * 4;
    const int bR  = tid >> 5;
    const int bC  = (tid & 31) * 4;

    float4 aReg[4], bReg[4];

    // prologue load kt=0
#pragma unroll
    for (int it = 0; it < 4; ++it) {
        const int r  = aR + it * 32;
        const int gr = rowN + r;
        aReg[it] = (gr < M) ? *(const float4*)&A[(size_t)gr * K + aC]
                            : make_float4(0.f, 0.f, 0.f, 0.f);
        bReg[it] = *(const float4*)&B[(size_t)(bR + it * 8) * ldb + colN + bC];
    }

    const int ktiles = K >> 5;
    for (int kt = 0; kt < ktiles; ++kt) {
        float* As = AsB[kt & 1];
        float* Bs = BsB[kt & 1];
        // STS with fused tf32 conversion
#pragma unroll
        for (int it = 0; it < 4; ++it) {
            float4 v = aReg[it];
            v.x = to_tf32(v.x); v.y = to_tf32(v.y);
            v.z = to_tf32(v.z); v.w = to_tf32(v.w);
            *(float4*)&As[(aR + it * 32) * AS_LD + aC] = v;
            float4 w = bReg[it];
            w.x = to_tf32(w.x); w.y = to_tf32(w.y);
            w.z = to_tf32(w.z); w.w = to_tf32(w.w);
            *(float4*)&Bs[(bR + it * 8) * BS_LD + bC] = w;
        }
        __syncthreads();

        // issue next k-tile's global loads (latency overlapped with MMA below)
        if (kt + 1 < ktiles) {
            const int ko = (kt + 1) << 5;
#pragma unroll
            for (int it = 0; it < 4; ++it) {
                const int r  = aR + it * 32;
                const int gr = rowN + r;
                aReg[it] = (gr < M) ? *(const float4*)&A[(size_t)gr * K + ko + aC]
                                    : make_float4(0.f, 0.f, 0.f, 0.f);
                bReg[it] = *(const float4*)&B[(size_t)(ko + bR + it * 8) * ldb + colN + bC];
            }
        }

#pragma unroll
        for (int ks = 0; ks < 4; ++ks) {
            wmma::fragment<wmma::matrix_a, 16, 16, 8, wmma::precision::tf32, wmma::row_major> a[4];
            wmma::fragment<wmma::matrix_b, 16, 16, 8, wmma::precision::tf32, wmma::row_major> b[2];
#pragma unroll
            for (int mi = 0; mi < 4; ++mi)
                wmma::load_matrix_sync(a[mi], &As[(wRow * 64 + mi * 16) * AS_LD + ks * 8], AS_LD);
#pragma unroll
            for (int ni = 0; ni < 2; ++ni)
                wmma::load_matrix_sync(b[ni], &Bs[(ks * 8) * BS_LD + wCol * 32 + ni * 16], BS_LD);
#pragma unroll
            for (int mi = 0; mi < 4; ++mi)
#pragma unroll
                for (int ni = 0; ni < 2; ++ni)
                    wmma::mma_sync(c[mi][ni], a[mi], b[ni], c[mi][ni]);
        }
        __syncthreads();   // buffer kt&1 free for reuse at kt+2
    }
}

// ---------------- generic GEMM: C = op(A@B + bias) -------------------------
__global__ __launch_bounds__(256) void gemm_tf32(
    const float* __restrict__ A, const float* __restrict__ B,
    float* __restrict__ C, const float* __restrict__ bias,
    int M, int K, int N, int ldb, int do_relu)
{
    const int tid    = threadIdx.x;
    const int warpId = tid >> 5;
    const int wRow   = warpId >> 2;
    const int wCol   = warpId & 3;
    const int rowN   = blockIdx.x * 128;
    const int colN   = blockIdx.y * 128;

    wmma::fragment<wmma::accumulator, 16, 16, 8, float> c[4][2];
#pragma unroll
    for (int mi = 0; mi < 4; ++mi)
#pragma unroll
        for (int ni = 0; ni < 2; ++ni) wmma::fill_fragment(c[mi][ni], 0.f);

    gemm_tile(A, B, M, K, ldb, rowN, colN, smem_dyn, c, wRow, wCol);

    // epilogue via smem (union with stage buffers; k-loop ended with sync)
    float* Cs = smem_dyn;
#pragma unroll
    for (int mi = 0; mi < 4; ++mi)
#pragma unroll
        for (int ni = 0; ni < 2; ++ni)
            wmma::store_matrix_sync(&Cs[(wRow * 64 + mi * 16) * CS_LD + wCol * 32 + ni * 16],
                                    c[mi][ni], CS_LD, wmma::mem_row_major);
    __syncthreads();

#pragma unroll
    for (int it = 0; it < 16; ++it) {
        const int i  = tid + it * 256;
        const int r  = i >> 5;
        const int c4 = i & 31;
        const int gr = rowN + r;
        if (gr < M) {
            float4 v = *(float4*)&Cs[r * CS_LD + c4 * 4];
            if (bias) {
                v.x += bias[colN + c4 * 4 + 0];
                v.y += bias[colN + c4 * 4 + 1];
                v.z += bias[colN + c4 * 4 + 2];
                v.w += bias[colN + c4 * 4 + 3];
            }
            if (do_relu) {
                v.x = fmaxf(v.x, 0.f); v.y = fmaxf(v.y, 0.f);
                v.z = fmaxf(v.z, 0.f); v.w = fmaxf(v.w, 0.f);
            }
            *(float4*)&C[(size_t)gr * N + colN + c4 * 4] = v;
        }
    }
}

// ---------------- fused: out = relu(A + E@Wbot + b_g1) @ Wf + bf -----------
__global__ __launch_bounds__(256) void gemm_final(
    const float* __restrict__ E, const float* __restrict__ Wbot,
    const float* __restrict__ AB, const float* __restrict__ bg,
    const float* __restrict__ Wf, const float* __restrict__ bf,
    float* __restrict__ out, int M)
{
    const int tid    = threadIdx.x;
    const int warpId = tid >> 5;
    const int wRow   = warpId >> 2;
    const int wCol   = warpId & 3;
    const int rowN   = blockIdx.x * 128;

    wmma::fragment<wmma::accumulator, 16, 16, 8, float> c[4][2];
#pragma unroll
    for (int mi = 0; mi < 4; ++mi)
#pragma unroll
        for (int ni = 0; ni < 2; ++ni) wmma::fill_fragment(c[mi][ni], 0.f);

    gemm_tile(E, Wbot, M, JDIM, JDIM, rowN, 0, smem_dyn, c, wRow, wCol);

    float* Cs = smem_dyn;
#pragma unroll
    for (int mi = 0; mi < 4; ++mi)
#pragma unroll
        for (int ni = 0; ni < 2; ++ni)
            wmma::store_matrix_sync(&Cs[(wRow * 64 + mi * 16) * CS_LD + wCol * 32 + ni * 16],
                                    c[mi][ni], CS_LD, wmma::mem_row_major);
    __syncthreads();

    // two threads per row; each covers 64 features, combine with one shfl
    const int r    = tid >> 1;
    const int half = tid & 1;
    const int f0   = half * 64;
    const int gr   = rowN + r;
    float s0 = 0.f, s1 = 0.f;
    if (gr < M) {
#pragma unroll
        for (int j = 0; j < 16; ++j) {
            const int f = f0 + j * 4;
            const float4 cv = *(float4*)&Cs[r * CS_LD + f];
            const float4 av = *(const float4*)&AB[(size_t)gr * 256 + f];  // A = H@Wtop
            const float e0 = fmaxf(av.x + cv.x + bg[f + 0], 0.f);
            const float e1 = fmaxf(av.y + cv.y + bg[f + 1], 0.f);
            const float e2 = fmaxf(av.z + cv.z + bg[f + 2], 0.f);
            const float e3 = fmaxf(av.w + cv.w + bg[f + 3], 0.f);
            s0 += e0 * Wf[(f + 0) * 2] + e1 * Wf[(f + 1) * 2]
                + e2 * Wf[(f + 2) * 2] + e3 * Wf[(f + 3) * 2];
            s1 += e0 * Wf[(f + 0) * 2 + 1] + e1 * Wf[(f + 1) * 2 + 1]
                + e2 * Wf[(f + 2) * 2 + 1] + e3 * Wf[(f + 3) * 2 + 1];
        }
    }
    s0 += __shfl_xor_sync(0xffffffffu, s0, 1);
    s1 += __shfl_xor_sync(0xffffffffu, s1, 1);
    if (half == 0 && gr < M) {
        out[(size_t)gr * 2 + 0] = s0 + bf[0];
        out[(size_t)gr * 2 + 1] = s1 + bf[1];
    }
}

// ---------------- build [Wtop | Wbot] (128 x 256) from W_g1 (256 x 128) ----
__global__ void build_wcat(const float* __restrict__ Wg)
{
    int i = blockIdx.x * blockDim.x + threadIdx.x;
    if (i >= JDIM * 2 * JDIM) return;
    int k = i >> 8;
    int n = i & 255;
    g_Wcat[i] = (n < JDIM) ? Wg[k * JDIM + n]
                           : Wg[(JDIM + k) * JDIM + (n - JDIM)];
}

// ---------------- E[l] = relu( mean_s relu(A[idx0]+B[idx1]+b_g1) ) ---------
__global__ __launch_bounds__(256) void gather_mean(
    const int* __restrict__ idx0, const int* __restrict__ idx1,
    const float* __restrict__ bg)
{
    const int warp = (blockIdx.x * blockDim.x + threadIdx.x) >> 5;
    const int lane = threadIdx.x & 31;
    if (warp >= L_NODES) return;
    const int c = lane * 4;
    const float b0 = bg[c], b1 = bg[c + 1], b2 = bg[c + 2], b3 = bg[c + 3];
    float4 acc = make_float4(0.f, 0.f, 0.f, 0.f);
#pragma unroll
    for (int s = 0; s < SSAMP; ++s) {
        const int i0 = idx0[s * L_NODES + warp];
        const int i1 = idx1[s * L_NODES + warp];
        const float4 a  = *(const float4*)&g_AB[(size_t)i0 * 256 + c];
        const float4 bb = *(const float4*)&g_AB[(size_t)i1 * 256 + 128 + c];
        acc.x += fmaxf(a.x + bb.x + b0, 0.f);
        acc.y += fmaxf(a.y + bb.y + b1, 0.f);
        acc.z += fmaxf(a.z + bb.z + b2, 0.f);
        acc.w += fmaxf(a.w + bb.w + b3, 0.f);
    }
    const float inv = 1.f / (float)SSAMP;
    float4 e;
    e.x = fmaxf(acc.x * inv, 0.f);
    e.y = fmaxf(acc.y * inv, 0.f);
    e.z = fmaxf(acc.z * inv, 0.f);
    e.w = fmaxf(acc.w * inv, 0.f);
    *(float4*)&g_E[(size_t)warp * JDIM + c] = e;
}

// ---------------------------------------------------------------------------
extern "C" void kernel_launch(void* const* d_in, const int* in_sizes, int n_in,
                              void* d_out, int out_size)
{
    const float* X    = (const float*)d_in[0];
    const float* Wh1  = (const float*)d_in[1];
    const float* bh1  = (const float*)d_in[2];
    const float* Wg1  = (const float*)d_in[3];
    const float* bg1  = (const float*)d_in[4];
    const float* Wf   = (const float*)d_in[5];
    const float* bf   = (const float*)d_in[6];
    const int*   idx0 = (const int*)d_in[7];
    const int*   idx1 = (const int*)d_in[8];
    float* out = (float*)d_out;

    float *H, *AB, *E, *Wcat;
    cudaGetSymbolAddress((void**)&H,    g_H);
    cudaGetSymbolAddress((void**)&AB,   g_AB);
    cudaGetSymbolAddress((void**)&E,    g_E);
    cudaGetSymbolAddress((void**)&Wcat, g_Wcat);

    cudaFuncSetAttribute(gemm_tf32, cudaFuncAttributeMaxDynamicSharedMemorySize, SMEM_BYTES);
    cudaFuncSetAttribute(gemm_final, cudaFuncAttributeMaxDynamicSharedMemorySize, SMEM_BYTES);

    const int mtiles = (L_NODES + 127) / 128;   // 782
    dim3 blk(256);

    build_wcat<<<(JDIM * 2 * JDIM + 255) / 256, 256>>>(Wg1);

    // 1) H = relu(X @ Wh1 + bh1)            (1e5,256)@(256,128)
    gemm_tf32<<<dim3(mtiles, 1), blk, SMEM_BYTES>>>(
        X, Wh1, H, bh1, L_NODES, NFEAT, JDIM, JDIM, 1);

    // 2) [A|B] = H @ [Wtop|Wbot]            (1e5,128)@(128,256)
    gemm_tf32<<<dim3(mtiles, 2), blk, SMEM_BYTES>>>(
        H, Wcat, AB, nullptr, L_NODES, JDIM, 2 * JDIM, 2 * JDIM, 0);

    // 3) E = relu(mean_s relu(A[idx0]+B[idx1]+b_g1))
    gather_mean<<<(L_NODES + 7) / 8, 256>>>(idx0, idx1, bg1);

    // 4+5) out = relu(A + E@Wbot + b_g1) @ Wf + bf   (fused)
    gemm_final<<<dim3(mtiles, 1), blk, SMEM_BYTES>>>(
        E, Wg1 + JDIM * JDIM, AB, bg1, Wf, bf, out, L_NODES);
}

// round 5
// speedup vs baseline: 3.4865x; 1.9306x over previous
#include <cuda_runtime.h>
#include <cuda_fp16.h>
#include <mma.h>
#include <cstddef>

using namespace nvcuda;

#define L_NODES 100000
#define NFEAT   256
#define JDIM    128
#define SSAMP   8

// ---------------- scratch (static __device__ — no allocations allowed) -----
__device__ float g_AB[(size_t)L_NODES * 2 * JDIM];   // 102.4 MB  [A|B]
__device__ float g_E[(size_t)L_NODES * JDIM];        //  51.2 MB

// ---------------- smem geometry (halves unless noted) ----------------------
#define AS_LD 40      // 32 + 8 pad halves (80B rows; conflict-free ldmatrix)
#define BS_LD 136     // 128 + 8 pad halves (272B rows)
#define HS_LD 136
#define CS_LD 132     // floats

#define AS_BYTES (128 * AS_LD * 2)        // 10240
#define BS_BYTES (32 * BS_LD * 2)         // 8704
#define H_OFF    0
#define H_BYTES  (128 * HS_LD * 2)        // 34816
#define WP_OFF   H_BYTES                  // 34816
#define WP_BYTES (128 * HS_LD * 2)        // 34816
#define SCR_OFF  (WP_OFF + WP_BYTES)      // 69632 (16B aligned)
#define CS_BYTES (128 * CS_LD * 4)        // 67584
#define SMEM_FUSED (SCR_OFF + CS_BYTES)   // 137216
#define SMEM_FINAL CS_BYTES               // 67584 (scratch-only layout)

extern __shared__ char smem_raw[];

// ---------------- fp16 mma core over smem tiles ----------------------------
// acc += Atile(128 x 32, ld ldA) @ Btile(32 x 128, ld ldB), two k=16 steps
__device__ __forceinline__ void mma_chunk(
    const __half* As, const __half* Bs, int ldA, int ldB,
    wmma::fragment<wmma::accumulator, 16, 16, 16, float> (&c)[4][2],
    int wRow, int wCol)
{
#pragma unroll
    for (int ks = 0; ks < 2; ++ks) {
        wmma::fragment<wmma::matrix_a, 16, 16, 16, __half, wmma::row_major> a[4];
        wmma::fragment<wmma::matrix_b, 16, 16, 16, __half, wmma::row_major> b[2];
#pragma unroll
        for (int mi = 0; mi < 4; ++mi)
            wmma::load_matrix_sync(a[mi], &As[(wRow * 64 + mi * 16) * ldA + ks * 16], ldA);
#pragma unroll
        for (int ni = 0; ni < 2; ++ni)
            wmma::load_matrix_sync(b[ni], &Bs[(ks * 16) * ldB + wCol * 32 + ni * 16], ldB);
#pragma unroll
        for (int mi = 0; mi < 4; ++mi)
#pragma unroll
            for (int ni = 0; ni < 2; ++ni)
                wmma::mma_sync(c[mi][ni], a[mi], b[ni], c[mi][ni]);
    }
}

__device__ __forceinline__ void sts_half4(__half* dst, float4 v)
{
    __half2 h[2];
    h[0] = __floats2half2_rn(v.x, v.y);
    h[1] = __floats2half2_rn(v.z, v.w);
    *(uint2*)dst = *(uint2*)h;
}

// Register-staged double-buffered K-loop: acc = A(MxK)@B(KxN=128 row-major)
__device__ __forceinline__ void gemm_half_pipeline(
    const float* __restrict__ A, const float* __restrict__ B,
    int M, int K, int rowN, char* scratch,
    wmma::fragment<wmma::accumulator, 16, 16, 16, float> (&c)[4][2],
    int wRow, int wCol)
{
    __half* AsB[2] = { (__half*)scratch, (__half*)(scratch + AS_BYTES) };
    __half* BsB[2] = { (__half*)(scratch + 2 * AS_BYTES),
                       (__half*)(scratch + 2 * AS_BYTES + BS_BYTES) };
    const int tid = threadIdx.x;
    const int aR  = tid >> 3;            // 0..31
    const int aC  = (tid & 7) * 4;
    const int bR  = tid >> 5;            // 0..7
    const int bC  = (tid & 31) * 4;

    float4 aReg[4], bReg[4];
#pragma unroll
    for (int it = 0; it < 4; ++it) {
        const int gr = rowN + aR + it * 32;
        aReg[it] = (gr < M) ? *(const float4*)&A[(size_t)gr * K + aC]
                            : make_float4(0.f, 0.f, 0.f, 0.f);
        bReg[it] = *(const float4*)&B[(size_t)(bR + it * 8) * 128 + bC];
    }

    const int ktiles = K >> 5;
    for (int kt = 0; kt < ktiles; ++kt) {
        __half* As = AsB[kt & 1];
        __half* Bs = BsB[kt & 1];
#pragma unroll
        for (int it = 0; it < 4; ++it) {
            sts_half4(&As[(aR + it * 32) * AS_LD + aC], aReg[it]);
            sts_half4(&Bs[(bR + it * 8) * BS_LD + bC], bReg[it]);
        }
        __syncthreads();
        if (kt + 1 < ktiles) {
            const int ko = (kt + 1) << 5;
#pragma unroll
            for (int it = 0; it < 4; ++it) {
                const int gr = rowN + aR + it * 32;
                aReg[it] = (gr < M) ? *(const float4*)&A[(size_t)gr * K + ko + aC]
                                    : make_float4(0.f, 0.f, 0.f, 0.f);
                bReg[it] = *(const float4*)&B[(size_t)(ko + bR + it * 8) * 128 + bC];
            }
        }
        mma_chunk(As, Bs, AS_LD, BS_LD, c, wRow, wCol);
        __syncthreads();
    }
}

// ---------------- fused: AB = ( relu(X@Wh1+b) ) @ [Wtop|Wbot] --------------
__global__ __launch_bounds__(256) void fused12(
    const float* __restrict__ X, const float* __restrict__ Wh1,
    const float* __restrict__ bh1, const float* __restrict__ Wg1,
    float* __restrict__ AB, int M)
{
    char* sm = smem_raw;
    __half* Hh = (__half*)(sm + H_OFF);
    __half* Wp = (__half*)(sm + WP_OFF);
    float*  Cs = (float*)(sm + SCR_OFF);

    const int tid  = threadIdx.x;
    const int wId  = tid >> 5;
    const int wRow = wId >> 2;
    const int wCol = wId & 3;
    const int rowN = blockIdx.x * 128;

    wmma::fragment<wmma::accumulator, 16, 16, 16, float> c[4][2];
#pragma unroll
    for (int mi = 0; mi < 4; ++mi)
#pragma unroll
        for (int ni = 0; ni < 2; ++ni) wmma::fill_fragment(c[mi][ni], 0.f);

    // ---- phase A: H accum = X[rowN:+128] @ Wh1 ----
    gemm_half_pipeline(X, Wh1, M, NFEAT, rowN, sm + SCR_OFF, c, wRow, wCol);

    // stage accum -> Cs(fp32) -> bias+relu -> H smem (fp16)
#pragma unroll
    for (int mi = 0; mi < 4; ++mi)
#pragma unroll
        for (int ni = 0; ni < 2; ++ni)
            wmma::store_matrix_sync(&Cs[(wRow * 64 + mi * 16) * CS_LD + wCol * 32 + ni * 16],
                                    c[mi][ni], CS_LD, wmma::mem_row_major);
    __syncthreads();
#pragma unroll
    for (int it = 0; it < 16; ++it) {
        const int i  = tid + it * 256;
        const int r  = i >> 5;
        const int c4 = (i & 31) * 4;
        float4 v = *(float4*)&Cs[r * CS_LD + c4];
        v.x = fmaxf(v.x + bh1[c4 + 0], 0.f);
        v.y = fmaxf(v.y + bh1[c4 + 1], 0.f);
        v.z = fmaxf(v.z + bh1[c4 + 2], 0.f);
        v.w = fmaxf(v.w + bh1[c4 + 3], 0.f);
        sts_half4(&Hh[r * HS_LD + c4], v);
    }
    __syncthreads();

    // ---- phase B: AB[:, h*128:+128] = H @ Wg1[h*128:+128, :] ----
    for (int h = 0; h < 2; ++h) {
        // load weight panel (128x128) fp32 -> fp16 smem
#pragma unroll
        for (int it = 0; it < 16; ++it) {
            const int i  = tid + it * 256;
            const int k  = i >> 5;
            const int n4 = (i & 31) * 4;
            float4 w = *(const float4*)&Wg1[(size_t)(h * 128 + k) * 128 + n4];
            sts_half4(&Wp[k * HS_LD + n4], w);
        }
        __syncthreads();

#pragma unroll
        for (int mi = 0; mi < 4; ++mi)
#pragma unroll
            for (int ni = 0; ni < 2; ++ni) wmma::fill_fragment(c[mi][ni], 0.f);
#pragma unroll
        for (int kc = 0; kc < 4; ++kc)   // 4 chunks of K=32
            mma_chunk(&Hh[kc * 32], &Wp[(kc * 32) * HS_LD], HS_LD, HS_LD, c, wRow, wCol);
        __syncthreads();

#pragma unroll
        for (int mi = 0; mi < 4; ++mi)
#pragma unroll
            for (int ni = 0; ni < 2; ++ni)
                wmma::store_matrix_sync(&Cs[(wRow * 64 + mi * 16) * CS_LD + wCol * 32 + ni * 16],
                                        c[mi][ni], CS_LD, wmma::mem_row_major);
        __syncthreads();
#pragma unroll
        for (int it = 0; it < 16; ++it) {
            const int i  = tid + it * 256;
            const int r  = i >> 5;
            const int c4 = (i & 31) * 4;
            const int gr = rowN + r;
            if (gr < M)
                *(float4*)&AB[(size_t)gr * 256 + h * 128 + c4] =
                    *(float4*)&Cs[r * CS_LD + c4];
        }
        __syncthreads();  // Cs/Wp free for next half
    }
}

// ---------------- E[l] = relu( mean_s relu(A[idx0]+B[idx1]+b_g1) ) ---------
__global__ __launch_bounds__(256) void gather_mean(
    const int* __restrict__ idx0, const int* __restrict__ idx1,
    const float* __restrict__ bg)
{
    const int warp = (blockIdx.x * blockDim.x + threadIdx.x) >> 5;
    const int lane = threadIdx.x & 31;
    if (warp >= L_NODES) return;
    const int c = lane * 4;
    const float b0 = bg[c], b1 = bg[c + 1], b2 = bg[c + 2], b3 = bg[c + 3];
    float4 acc = make_float4(0.f, 0.f, 0.f, 0.f);
#pragma unroll
    for (int s = 0; s < SSAMP; ++s) {
        const int i0 = idx0[s * L_NODES + warp];
        const int i1 = idx1[s * L_NODES + warp];
        const float4 a  = *(const float4*)&g_AB[(size_t)i0 * 256 + c];
        const float4 bb = *(const float4*)&g_AB[(size_t)i1 * 256 + 128 + c];
        acc.x += fmaxf(a.x + bb.x + b0, 0.f);
        acc.y += fmaxf(a.y + bb.y + b1, 0.f);
        acc.z += fmaxf(a.z + bb.z + b2, 0.f);
        acc.w += fmaxf(a.w + bb.w + b3, 0.f);
    }
    const float inv = 1.f / (float)SSAMP;
    float4 e;
    e.x = fmaxf(acc.x * inv, 0.f);
    e.y = fmaxf(acc.y * inv, 0.f);
    e.z = fmaxf(acc.z * inv, 0.f);
    e.w = fmaxf(acc.w * inv, 0.f);
    *(float4*)&g_E[(size_t)warp * JDIM + c] = e;
}

// ---------------- fused: out = relu(A + E@Wbot + b_g1) @ Wf + bf -----------
__global__ __launch_bounds__(256) void gemm_final(
    const float* __restrict__ E, const float* __restrict__ Wbot,
    const float* __restrict__ AB, const float* __restrict__ bg,
    const float* __restrict__ Wf, const float* __restrict__ bf,
    float* __restrict__ out, int M)
{
    char* sm = smem_raw;
    float* Cs = (float*)sm;

    const int tid  = threadIdx.x;
    const int wId  = tid >> 5;
    const int wRow = wId >> 2;
    const int wCol = wId & 3;
    const int rowN = blockIdx.x * 128;

    wmma::fragment<wmma::accumulator, 16, 16, 16, float> c[4][2];
#pragma unroll
    for (int mi = 0; mi < 4; ++mi)
#pragma unroll
        for (int ni = 0; ni < 2; ++ni) wmma::fill_fragment(c[mi][ni], 0.f);

    gemm_half_pipeline(E, Wbot, M, JDIM, rowN, sm, c, wRow, wCol);

#pragma unroll
    for (int mi = 0; mi < 4; ++mi)
#pragma unroll
        for (int ni = 0; ni < 2; ++ni)
            wmma::store_matrix_sync(&Cs[(wRow * 64 + mi * 16) * CS_LD + wCol * 32 + ni * 16],
                                    c[mi][ni], CS_LD, wmma::mem_row_major);
    __syncthreads();

    // two threads per row; each covers 64 features, combine with one shfl
    const int r    = tid >> 1;
    const int half = tid & 1;
    const int f0   = half * 64;
    const int gr   = rowN + r;
    float s0 = 0.f, s1 = 0.f;
    if (gr < M) {
#pragma unroll
        for (int j = 0; j < 16; ++j) {
            const int f = f0 + j * 4;
            const float4 cv = *(float4*)&Cs[r * CS_LD + f];
            const float4 av = *(const float4*)&AB[(size_t)gr * 256 + f];  // A = H@Wtop
            const float e0 = fmaxf(av.x + cv.x + bg[f + 0], 0.f);
            const float e1 = fmaxf(av.y + cv.y + bg[f + 1], 0.f);
            const float e2 = fmaxf(av.z + cv.z + bg[f + 2], 0.f);
            const float e3 = fmaxf(av.w + cv.w + bg[f + 3], 0.f);
            s0 += e0 * Wf[(f + 0) * 2] + e1 * Wf[(f + 1) * 2]
                + e2 * Wf[(f + 2) * 2] + e3 * Wf[(f + 3) * 2];
            s1 += e0 * Wf[(f + 0) * 2 + 1] + e1 * Wf[(f + 1) * 2 + 1]
                + e2 * Wf[(f + 2) * 2 + 1] + e3 * Wf[(f + 3) * 2 + 1];
        }
    }
    s0 += __shfl_xor_sync(0xffffffffu, s0, 1);
    s1 += __shfl_xor_sync(0xffffffffu, s1, 1);
    if (half == 0 && gr < M) {
        out[(size_t)gr * 2 + 0] = s0 + bf[0];
        out[(size_t)gr * 2 + 1] = s1 + bf[1];
    }
}

// ---------------------------------------------------------------------------
extern "C" void kernel_launch(void* const* d_in, const int* in_sizes, int n_in,
                              void* d_out, int out_size)
{
    const float* X    = (const float*)d_in[0];
    const float* Wh1  = (const float*)d_in[1];
    const float* bh1  = (const float*)d_in[2];
    const float* Wg1  = (const float*)d_in[3];
    const float* bg1  = (const float*)d_in[4];
    const float* Wf   = (const float*)d_in[5];
    const float* bf   = (const float*)d_in[6];
    const int*   idx0 = (const int*)d_in[7];
    const int*   idx1 = (const int*)d_in[8];
    float* out = (float*)d_out;

    float *AB, *E;
    cudaGetSymbolAddress((void**)&AB, g_AB);
    cudaGetSymbolAddress((void**)&E,  g_E);

    cudaFuncSetAttribute(fused12, cudaFuncAttributeMaxDynamicSharedMemorySize, SMEM_FUSED);
    cudaFuncSetAttribute(gemm_final, cudaFuncAttributeMaxDynamicSharedMemorySize, SMEM_FINAL);

    const int mtiles = (L_NODES + 127) / 128;   // 782
    dim3 blk(256);

    // 1+2) AB = relu(X@Wh1+bh1) @ [Wtop|Wbot]   (H never hits gmem)
    fused12<<<mtiles, blk, SMEM_FUSED>>>(X, Wh1, bh1, Wg1, AB, L_NODES);

    // 3) E = relu(mean_s relu(A[idx0]+B[idx1]+b_g1))
    gather_mean<<<(L_NODES + 7) / 8, 256>>>(idx0, idx1, bg1);

    // 4+5) out = relu(A + E@Wbot + b_g1) @ Wf + bf
    gemm_final<<<mtiles, blk, SMEM_FINAL>>>(
        E, Wg1 + JDIM * JDIM, AB, bg1, Wf, bf, out, L_NODES);
}

// round 6
// speedup vs baseline: 4.3198x; 1.2390x over previous
#include <cuda_runtime.h>
#include <cuda_fp16.h>
#include <mma.h>
#include <cstddef>

using namespace nvcuda;

#define L_NODES 100000
#define NFEAT   256
#define JDIM    128
#define SSAMP   8
#define NTHREADS 512

// ---------------- scratch (static __device__ — no allocations allowed) -----
__device__ __half g_ABh[(size_t)L_NODES * 2 * JDIM];  // 51.2 MB  [A|B] fp16
__device__ float  g_E[(size_t)L_NODES * JDIM];        // 51.2 MB

// ---------------- smem geometry (halves unless noted) ----------------------
#define AS_LD 40      // 32 + 8 pad halves
#define BS_LD 136     // 128 + 8 pad halves
#define HS_LD 136
#define CS_LD 132     // floats

#define AS_BYTES (128 * AS_LD * 2)        // 10240
#define BS_BYTES (32 * BS_LD * 2)         // 8704
#define H_OFF    0
#define H_BYTES  (128 * HS_LD * 2)        // 34816
#define WP_OFF   H_BYTES
#define WP_BYTES (128 * HS_LD * 2)
#define SCR_OFF  (WP_OFF + WP_BYTES)      // 69632
#define CS_BYTES (128 * CS_LD * 4)        // 67584
#define SMEM_FUSED (SCR_OFF + CS_BYTES)   // 137216
#define SMEM_FINAL CS_BYTES

extern __shared__ char smem_raw[];

// ---------------- fp16 mma core: warp tile 32x32 over smem tiles -----------
__device__ __forceinline__ void mma_chunk32(
    const __half* As, const __half* Bs, int ldA, int ldB,
    wmma::fragment<wmma::accumulator, 16, 16, 16, float> (&c)[2][2],
    int wRow, int wCol)
{
#pragma unroll
    for (int ks = 0; ks < 2; ++ks) {
        wmma::fragment<wmma::matrix_a, 16, 16, 16, __half, wmma::row_major> a[2];
        wmma::fragment<wmma::matrix_b, 16, 16, 16, __half, wmma::row_major> b[2];
#pragma unroll
        for (int mi = 0; mi < 2; ++mi)
            wmma::load_matrix_sync(a[mi], &As[(wRow * 32 + mi * 16) * ldA + ks * 16], ldA);
#pragma unroll
        for (int ni = 0; ni < 2; ++ni)
            wmma::load_matrix_sync(b[ni], &Bs[(ks * 16) * ldB + wCol * 32 + ni * 16], ldB);
#pragma unroll
        for (int mi = 0; mi < 2; ++mi)
#pragma unroll
            for (int ni = 0; ni < 2; ++ni)
                wmma::mma_sync(c[mi][ni], a[mi], b[ni], c[mi][ni]);
    }
}

__device__ __forceinline__ void sts_half4(__half* dst, float4 v)
{
    __half2 h[2];
    h[0] = __floats2half2_rn(v.x, v.y);
    h[1] = __floats2half2_rn(v.z, v.w);
    *(uint2*)dst = *(uint2*)h;
}

// Register-staged double-buffered K-loop (512 threads): acc = A(MxK)@B(KxN=128)
__device__ __forceinline__ void gemm_half_pipeline(
    const float* __restrict__ A, const float* __restrict__ B,
    int M, int K, int rowN, char* scratch,
    wmma::fragment<wmma::accumulator, 16, 16, 16, float> (&c)[2][2],
    int wRow, int wCol)
{
    __half* AsB[2] = { (__half*)scratch, (__half*)(scratch + AS_BYTES) };
    __half* BsB[2] = { (__half*)(scratch + 2 * AS_BYTES),
                       (__half*)(scratch + 2 * AS_BYTES + BS_BYTES) };
    const int tid = threadIdx.x;
    // A tile 128x32: 1024 float4 slots, 2 per thread
    const int aR0 = tid >> 2;            // 0..127
    const int aC0 = (tid & 3) * 4;       // slot half (cols 0..15); +16 on it=1
    // B tile 32x128: 1024 float4 slots, 2 per thread
    const int bR0 = tid >> 5;            // 0..15 ; +16 on it=1
    const int bC0 = (tid & 31) * 4;

    float4 aReg[2], bReg[2];
#pragma unroll
    for (int it = 0; it < 2; ++it) {
        const int gr = rowN + aR0;
        aReg[it] = (gr < M) ? *(const float4*)&A[(size_t)gr * K + aC0 + it * 16]
                            : make_float4(0.f, 0.f, 0.f, 0.f);
        bReg[it] = *(const float4*)&B[(size_t)(bR0 + it * 16) * 128 + bC0];
    }

    const int ktiles = K >> 5;
    for (int kt = 0; kt < ktiles; ++kt) {
        __half* As = AsB[kt & 1];
        __half* Bs = BsB[kt & 1];
#pragma unroll
        for (int it = 0; it < 2; ++it) {
            sts_half4(&As[aR0 * AS_LD + aC0 + it * 16], aReg[it]);
            sts_half4(&Bs[(bR0 + it * 16) * BS_LD + bC0], bReg[it]);
        }
        __syncthreads();
        if (kt + 1 < ktiles) {
            const int ko = (kt + 1) << 5;
#pragma unroll
            for (int it = 0; it < 2; ++it) {
                const int gr = rowN + aR0;
                aReg[it] = (gr < M) ? *(const float4*)&A[(size_t)gr * K + ko + aC0 + it * 16]
                                    : make_float4(0.f, 0.f, 0.f, 0.f);
                bReg[it] = *(const float4*)&B[(size_t)(ko + bR0 + it * 16) * 128 + bC0];
            }
        }
        mma_chunk32(As, Bs, AS_LD, BS_LD, c, wRow, wCol);
        __syncthreads();
    }
}

// ---------------- fused: ABh = fp16( relu(X@Wh1+b) @ [Wtop|Wbot] ) ---------
__global__ __launch_bounds__(NTHREADS) void fused12(
    const float* __restrict__ X, const float* __restrict__ Wh1,
    const float* __restrict__ bh1, const float* __restrict__ Wg1,
    __half* __restrict__ ABh, int M)
{
    char* sm = smem_raw;
    __half* Hh = (__half*)(sm + H_OFF);
    __half* Wp = (__half*)(sm + WP_OFF);
    float*  Cs = (float*)(sm + SCR_OFF);

    const int tid  = threadIdx.x;
    const int wId  = tid >> 5;
    const int wRow = wId >> 2;           // 0..3
    const int wCol = wId & 3;            // 0..3
    const int rowN = blockIdx.x * 128;

    wmma::fragment<wmma::accumulator, 16, 16, 16, float> c[2][2];
#pragma unroll
    for (int mi = 0; mi < 2; ++mi)
#pragma unroll
        for (int ni = 0; ni < 2; ++ni) wmma::fill_fragment(c[mi][ni], 0.f);

    // ---- phase A: accum = X[rowN:+128] @ Wh1 ----
    gemm_half_pipeline(X, Wh1, M, NFEAT, rowN, sm + SCR_OFF, c, wRow, wCol);

    // stage accum -> Cs(fp32) -> bias+relu -> H smem (fp16)
#pragma unroll
    for (int mi = 0; mi < 2; ++mi)
#pragma unroll
        for (int ni = 0; ni < 2; ++ni)
            wmma::store_matrix_sync(&Cs[(wRow * 32 + mi * 16) * CS_LD + wCol * 32 + ni * 16],
                                    c[mi][ni], CS_LD, wmma::mem_row_major);
    __syncthreads();
#pragma unroll
    for (int it = 0; it < 8; ++it) {
        const int i  = tid + it * NTHREADS;
        const int r  = i >> 5;
        const int c4 = (i & 31) * 4;
        float4 v = *(float4*)&Cs[r * CS_LD + c4];
        v.x = fmaxf(v.x + bh1[c4 + 0], 0.f);
        v.y = fmaxf(v.y + bh1[c4 + 1], 0.f);
        v.z = fmaxf(v.z + bh1[c4 + 2], 0.f);
        v.w = fmaxf(v.w + bh1[c4 + 3], 0.f);
        sts_half4(&Hh[r * HS_LD + c4], v);
    }
    __syncthreads();

    // ---- phase B: AB[:, h*128:+128] = H @ Wg1[h*128:+128, :] ----
    for (int h = 0; h < 2; ++h) {
        // weight panel (128x128) fp32 -> fp16 smem
#pragma unroll
        for (int it = 0; it < 8; ++it) {
            const int i  = tid + it * NTHREADS;
            const int k  = i >> 5;
            const int n4 = (i & 31) * 4;
            float4 w = *(const float4*)&Wg1[(size_t)(h * 128 + k) * 128 + n4];
            sts_half4(&Wp[k * HS_LD + n4], w);
        }
        __syncthreads();

#pragma unroll
        for (int mi = 0; mi < 2; ++mi)
#pragma unroll
            for (int ni = 0; ni < 2; ++ni) wmma::fill_fragment(c[mi][ni], 0.f);
#pragma unroll
        for (int kc = 0; kc < 4; ++kc)
            mma_chunk32(&Hh[kc * 32], &Wp[(kc * 32) * HS_LD], HS_LD, HS_LD, c, wRow, wCol);
        __syncthreads();

#pragma unroll
        for (int mi = 0; mi < 2; ++mi)
#pragma unroll
            for (int ni = 0; ni < 2; ++ni)
                wmma::store_matrix_sync(&Cs[(wRow * 32 + mi * 16) * CS_LD + wCol * 32 + ni * 16],
                                        c[mi][ni], CS_LD, wmma::mem_row_major);
        __syncthreads();
#pragma unroll
        for (int it = 0; it < 8; ++it) {
            const int i  = tid + it * NTHREADS;
            const int r  = i >> 5;
            const int c4 = (i & 31) * 4;
            const int gr = rowN + r;
            if (gr < M) {
                float4 v = *(float4*)&Cs[r * CS_LD + c4];
                sts_half4(&ABh[(size_t)gr * 256 + h * 128 + c4], v);  // global store
            }
        }
        __syncthreads();
    }
}

// ---------------- E[l] = relu( mean_s relu(A[idx0]+B[idx1]+b_g1) ) ---------
__global__ __launch_bounds__(256) void gather_mean(
    const int* __restrict__ idx0, const int* __restrict__ idx1,
    const float* __restrict__ bg)
{
    const int warp = (blockIdx.x * blockDim.x + threadIdx.x) >> 5;
    const int lane = threadIdx.x & 31;
    if (warp >= L_NODES) return;
    const int c = lane * 4;
    const float b0 = bg[c], b1 = bg[c + 1], b2 = bg[c + 2], b3 = bg[c + 3];
    float4 acc = make_float4(0.f, 0.f, 0.f, 0.f);
#pragma unroll
    for (int s = 0; s < SSAMP; ++s) {
        const int i0 = idx0[s * L_NODES + warp];
        const int i1 = idx1[s * L_NODES + warp];
        const uint2 au = *(const uint2*)&g_ABh[(size_t)i0 * 256 + c];
        const uint2 bu = *(const uint2*)&g_ABh[(size_t)i1 * 256 + 128 + c];
        const float2 a01 = __half22float2(*(const __half2*)&au.x);
        const float2 a23 = __half22float2(*(const __half2*)&au.y);
        const float2 b01 = __half22float2(*(const __half2*)&bu.x);
        const float2 b23 = __half22float2(*(const __half2*)&bu.y);
        acc.x += fmaxf(a01.x + b01.x + b0, 0.f);
        acc.y += fmaxf(a01.y + b01.y + b1, 0.f);
        acc.z += fmaxf(a23.x + b23.x + b2, 0.f);
        acc.w += fmaxf(a23.y + b23.y + b3, 0.f);
    }
    const float inv = 1.f / (float)SSAMP;
    float4 e;
    e.x = fmaxf(acc.x * inv, 0.f);
    e.y = fmaxf(acc.y * inv, 0.f);
    e.z = fmaxf(acc.z * inv, 0.f);
    e.w = fmaxf(acc.w * inv, 0.f);
    *(float4*)&g_E[(size_t)warp * JDIM + c] = e;
}

// ---------------- fused: out = relu(A + E@Wbot + b_g1) @ Wf + bf -----------
__global__ __launch_bounds__(NTHREADS) void gemm_final(
    const float* __restrict__ E, const float* __restrict__ Wbot,
    const __half* __restrict__ ABh, const float* __restrict__ bg,
    const float* __restrict__ Wf, const float* __restrict__ bf,
    float* __restrict__ out, int M)
{
    char* sm = smem_raw;
    float* Cs = (float*)sm;

    const int tid  = threadIdx.x;
    const int wId  = tid >> 5;
    const int wRow = wId >> 2;
    const int wCol = wId & 3;
    const int rowN = blockIdx.x * 128;

    wmma::fragment<wmma::accumulator, 16, 16, 16, float> c[2][2];
#pragma unroll
    for (int mi = 0; mi < 2; ++mi)
#pragma unroll
        for (int ni = 0; ni < 2; ++ni) wmma::fill_fragment(c[mi][ni], 0.f);

    gemm_half_pipeline(E, Wbot, M, JDIM, rowN, sm, c, wRow, wCol);

#pragma unroll
    for (int mi = 0; mi < 2; ++mi)
#pragma unroll
        for (int ni = 0; ni < 2; ++ni)
            wmma::store_matrix_sync(&Cs[(wRow * 32 + mi * 16) * CS_LD + wCol * 32 + ni * 16],
                                    c[mi][ni], CS_LD, wmma::mem_row_major);
    __syncthreads();

    // 4 threads per row; each covers 32 features; reduce with 2 shfls
    const int r  = tid >> 2;             // 0..127
    const int q  = tid & 3;
    const int f0 = q * 32;
    const int gr = rowN + r;
    float s0 = 0.f, s1 = 0.f;
    if (gr < M) {
#pragma unroll
        for (int j = 0; j < 8; ++j) {
            const int f = f0 + j * 4;
            const float4 cv = *(float4*)&Cs[r * CS_LD + f];
            const uint2 au = *(const uint2*)&ABh[(size_t)gr * 256 + f];  // A = H@Wtop
            const float2 a01 = __half22float2(*(const __half2*)&au.x);
            const float2 a23 = __half22float2(*(const __half2*)&au.y);
            const float e0 = fmaxf(a01.x + cv.x + bg[f + 0], 0.f);
            const float e1 = fmaxf(a01.y + cv.y + bg[f + 1], 0.f);
            const float e2 = fmaxf(a23.x + cv.z + bg[f + 2], 0.f);
            const float e3 = fmaxf(a23.y + cv.w + bg[f + 3], 0.f);
            s0 += e0 * Wf[(f + 0) * 2] + e1 * Wf[(f + 1) * 2]
                + e2 * Wf[(f + 2) * 2] + e3 * Wf[(f + 3) * 2];
            s1 += e0 * Wf[(f + 0) * 2 + 1] + e1 * Wf[(f + 1) * 2 + 1]
                + e2 * Wf[(f + 2) * 2 + 1] + e3 * Wf[(f + 3) * 2 + 1];
        }
    }
#pragma unroll
    for (int off = 1; off <= 2; off <<= 1) {
        s0 += __shfl_xor_sync(0xffffffffu, s0, off);
        s1 += __shfl_xor_sync(0xffffffffu, s1, off);
    }
    if (q == 0 && gr < M) {
        out[(size_t)gr * 2 + 0] = s0 + bf[0];
        out[(size_t)gr * 2 + 1] = s1 + bf[1];
    }
}

// ---------------------------------------------------------------------------
extern "C" void kernel_launch(void* const* d_in, const int* in_sizes, int n_in,
                              void* d_out, int out_size)
{
    const float* X    = (const float*)d_in[0];
    const float* Wh1  = (const float*)d_in[1];
    const float* bh1  = (const float*)d_in[2];
    const float* Wg1  = (const float*)d_in[3];
    const float* bg1  = (const float*)d_in[4];
    const float* Wf   = (const float*)d_in[5];
    const float* bf   = (const float*)d_in[6];
    const int*   idx0 = (const int*)d_in[7];
    const int*   idx1 = (const int*)d_in[8];
    float* out = (float*)d_out;

    __half* ABh;
    float*  E;
    cudaGetSymbolAddress((void**)&ABh, g_ABh);
    cudaGetSymbolAddress((void**)&E,   g_E);

    cudaFuncSetAttribute(fused12, cudaFuncAttributeMaxDynamicSharedMemorySize, SMEM_FUSED);
    cudaFuncSetAttribute(gemm_final, cudaFuncAttributeMaxDynamicSharedMemorySize, SMEM_FINAL);

    const int mtiles = (L_NODES + 127) / 128;   // 782

    // 1+2) ABh = fp16( relu(X@Wh1+bh1) @ [Wtop|Wbot] )
    fused12<<<mtiles, NTHREADS, SMEM_FUSED>>>(X, Wh1, bh1, Wg1, ABh, L_NODES);

    // 3) E = relu(mean_s relu(A[idx0]+B[idx1]+b_g1))
    gather_mean<<<(L_NODES + 7) / 8, 256>>>(idx0, idx1, bg1);

    // 4+5) out = relu(A + E@Wbot + b_g1) @ Wf + bf
    gemm_final<<<mtiles, NTHREADS, SMEM_FINAL>>>(
        E, Wg1 + JDIM * JDIM, ABh, bg1, Wf, bf, out, L_NODES);
}

// round 7
// speedup vs baseline: 4.9526x; 1.1465x over previous
#include <cuda_runtime.h>
#include <cuda_fp16.h>
#include <mma.h>
#include <cstddef>

using namespace nvcuda;

#define L_NODES 100000
#define NFEAT   256
#define JDIM    128
#define SSAMP   8
#define MTILE   64
#define NTHREADS 256

// ---------------- scratch (static __device__ — no allocations allowed) -----
__device__ __half g_ABh[(size_t)L_NODES * 2 * JDIM];  // 51.2 MB  [A|B] fp16
__device__ __half g_W1h[NFEAT * JDIM];                // Wh1 fp16 (256x128)
__device__ __half g_Wgh[2 * JDIM * JDIM];             // Wg1 fp16 (256x128)

// ---------------- smem geometry (halves unless noted) ----------------------
#define AS_LD 40      // 32 + 8 pad halves
#define BS_LD 136     // 128 + 8 pad halves
#define HS_LD 136
#define WP_LD 136
#define CS_LD 132     // floats

#define H_BYTES   (MTILE * HS_LD * 2)          // 17408
#define SCR_OFF   H_BYTES
#define AS_BYTES  (MTILE * AS_LD * 2)          // 5120
#define BS_BYTES  (32 * BS_LD * 2)             // 8704
#define WP_BYTES  (128 * WP_LD * 2)            // 34816
#define CS_BYTES  (MTILE * CS_LD * 4)          // 33792
#define SMEM_TOTAL (SCR_OFF + WP_BYTES)        // 52224  (union: scratch|Wp|Cs)

extern __shared__ char smem_raw[];

// ---------------- fp16 mma core: warp tile 32x32 ---------------------------
__device__ __forceinline__ void mma_chunk32(
    const __half* As, const __half* Bs, int ldA, int ldB,
    wmma::fragment<wmma::accumulator, 16, 16, 16, float> (&c)[2][2],
    int wRow, int wCol)
{
#pragma unroll
    for (int ks = 0; ks < 2; ++ks) {
        wmma::fragment<wmma::matrix_a, 16, 16, 16, __half, wmma::row_major> a[2];
        wmma::fragment<wmma::matrix_b, 16, 16, 16, __half, wmma::row_major> b[2];
#pragma unroll
        for (int mi = 0; mi < 2; ++mi)
            wmma::load_matrix_sync(a[mi], &As[(wRow * 32 + mi * 16) * ldA + ks * 16], ldA);
#pragma unroll
        for (int ni = 0; ni < 2; ++ni)
            wmma::load_matrix_sync(b[ni], &Bs[(ks * 16) * ldB + wCol * 32 + ni * 16], ldB);
#pragma unroll
        for (int mi = 0; mi < 2; ++mi)
#pragma unroll
            for (int ni = 0; ni < 2; ++ni)
                wmma::mma_sync(c[mi][ni], a[mi], b[ni], c[mi][ni]);
    }
}

__device__ __forceinline__ void sts_half4(__half* dst, float4 v)
{
    __half2 h[2];
    h[0] = __floats2half2_rn(v.x, v.y);
    h[1] = __floats2half2_rn(v.z, v.w);
    *(uint2*)dst = *(uint2*)h;
}

// ---------------- weight fp32 -> fp16 prepass ------------------------------
__global__ void convert_w(const float* __restrict__ Wh1, const float* __restrict__ Wg1)
{
    const int i = blockIdx.x * 256 + threadIdx.x;   // 0..32767
    g_W1h[i] = __float2half(Wh1[i]);
    g_Wgh[i] = __float2half(Wg1[i]);
}

// ---------------- fused12: ABh = fp16( relu(X@Wh1+b) @ [Wtop|Wbot] ) -------
__global__ __launch_bounds__(NTHREADS, 2) void fused12(
    const float* __restrict__ X, const float* __restrict__ bh1,
    __half* __restrict__ ABh, int M)
{
    char* sm = smem_raw;
    __half* Hh  = (__half*)sm;
    char*   scr = sm + SCR_OFF;
    __half* AsB[2] = { (__half*)scr, (__half*)(scr + AS_BYTES) };
    __half* BsB[2] = { (__half*)(scr + 2 * AS_BYTES),
                       (__half*)(scr + 2 * AS_BYTES + BS_BYTES) };
    float*  Cs = (float*)scr;
    __half* Wp = (__half*)scr;

    const int tid  = threadIdx.x;
    const int wId  = tid >> 5;
    const int wRow = wId >> 2;           // 0..1
    const int wCol = wId & 3;            // 0..3
    const int rowN = blockIdx.x * MTILE;

    const int aR  = tid >> 2;            // 0..63
    const int aC  = (tid & 3) * 4;       // +16 on it=1
    const int bR  = tid >> 4;            // 0..15 ; +16 on it=1
    const int bc8 = (tid & 15) * 8;      // halves

    wmma::fragment<wmma::accumulator, 16, 16, 16, float> c[2][2];
#pragma unroll
    for (int mi = 0; mi < 2; ++mi)
#pragma unroll
        for (int ni = 0; ni < 2; ++ni) wmma::fill_fragment(c[mi][ni], 0.f);

    // ---- phase A: acc = X[rowN:+64] @ Wh1 (K=256, 8 chunks of 32) ----
    const int gr = rowN + aR;
    float4 aReg[2];
    uint4  bReg[2];
#pragma unroll
    for (int it = 0; it < 2; ++it) {
        aReg[it] = (gr < M) ? *(const float4*)&X[(size_t)gr * NFEAT + aC + it * 16]
                            : make_float4(0.f, 0.f, 0.f, 0.f);
        bReg[it] = *(const uint4*)&g_W1h[(bR + it * 16) * JDIM + bc8];
    }
#pragma unroll
    for (int kt = 0; kt < 8; ++kt) {
        __half* As = AsB[kt & 1];
        __half* Bs = BsB[kt & 1];
#pragma unroll
        for (int it = 0; it < 2; ++it) {
            sts_half4(&As[aR * AS_LD + aC + it * 16], aReg[it]);
            *(uint4*)&Bs[(bR + it * 16) * BS_LD + bc8] = bReg[it];
        }
        __syncthreads();
        if (kt < 7) {
            const int ko = (kt + 1) * 32;
#pragma unroll
            for (int it = 0; it < 2; ++it) {
                aReg[it] = (gr < M) ? *(const float4*)&X[(size_t)gr * NFEAT + ko + aC + it * 16]
                                    : make_float4(0.f, 0.f, 0.f, 0.f);
                bReg[it] = *(const uint4*)&g_W1h[(ko + bR + it * 16) * JDIM + bc8];
            }
        }
        mma_chunk32(As, Bs, AS_LD, BS_LD, c, wRow, wCol);
        __syncthreads();
    }

    // stage acc -> Cs -> bias+relu -> Hh(fp16)
#pragma unroll
    for (int mi = 0; mi < 2; ++mi)
#pragma unroll
        for (int ni = 0; ni < 2; ++ni)
            wmma::store_matrix_sync(&Cs[(wRow * 32 + mi * 16) * CS_LD + wCol * 32 + ni * 16],
                                    c[mi][ni], CS_LD, wmma::mem_row_major);
    __syncthreads();
#pragma unroll
    for (int it = 0; it < 8; ++it) {
        const int i  = tid + it * NTHREADS;
        const int r  = i >> 5;
        const int c4 = (i & 31) * 4;
        float4 v = *(float4*)&Cs[r * CS_LD + c4];
        v.x = fmaxf(v.x + bh1[c4 + 0], 0.f);
        v.y = fmaxf(v.y + bh1[c4 + 1], 0.f);
        v.z = fmaxf(v.z + bh1[c4 + 2], 0.f);
        v.w = fmaxf(v.w + bh1[c4 + 3], 0.f);
        sts_half4(&Hh[r * HS_LD + c4], v);
    }
    __syncthreads();

    // ---- phase B: AB[:, h*128:+128] = H @ Wg1[h*128:+128, :] ----
#pragma unroll
    for (int h = 0; h < 2; ++h) {
        // weight panel 128x128 fp16 -> smem (uint4 copy, 8/thread)
#pragma unroll
        for (int it = 0; it < 8; ++it) {
            const int i  = tid + it * NTHREADS;
            const int k  = i >> 4;
            const int c8 = (i & 15) * 8;
            *(uint4*)&Wp[k * WP_LD + c8] = *(const uint4*)&g_Wgh[(size_t)(h * 128 + k) * JDIM + c8];
        }
        __syncthreads();

#pragma unroll
        for (int mi = 0; mi < 2; ++mi)
#pragma unroll
            for (int ni = 0; ni < 2; ++ni) wmma::fill_fragment(c[mi][ni], 0.f);
#pragma unroll
        for (int kc = 0; kc < 4; ++kc)
            mma_chunk32(&Hh[kc * 32], &Wp[(kc * 32) * WP_LD], HS_LD, WP_LD, c, wRow, wCol);
        __syncthreads();  // Wp reads done -> Cs may overwrite

#pragma unroll
        for (int mi = 0; mi < 2; ++mi)
#pragma unroll
            for (int ni = 0; ni < 2; ++ni)
                wmma::store_matrix_sync(&Cs[(wRow * 32 + mi * 16) * CS_LD + wCol * 32 + ni * 16],
                                        c[mi][ni], CS_LD, wmma::mem_row_major);
        __syncthreads();
#pragma unroll
        for (int it = 0; it < 8; ++it) {
            const int i  = tid + it * NTHREADS;
            const int r  = i >> 5;
            const int c4 = (i & 31) * 4;
            const int g2 = rowN + r;
            if (g2 < M)
                sts_half4(&ABh[(size_t)g2 * 256 + h * 128 + c4], *(float4*)&Cs[r * CS_LD + c4]);
        }
        __syncthreads();  // Cs free before next h
    }
}

// ---------------- final: gather -> E tile(smem) -> GEMM -> Wf epilogue -----
// out = relu( A + relu(mean_s relu(A[idx0]+B[idx1]+bg)) @ Wbot + bg ) @ Wf + bf
__global__ __launch_bounds__(NTHREADS, 2) void final_fused(
    const int* __restrict__ idx0, const int* __restrict__ idx1,
    const float* __restrict__ bg, const float* __restrict__ Wf,
    const float* __restrict__ bf, const __half* __restrict__ ABh,
    float* __restrict__ out, int M)
{
    char* sm = smem_raw;
    __half* Eh = (__half*)sm;
    __half* Wp = (__half*)(sm + SCR_OFF);
    float*  Cs = (float*)(sm + SCR_OFF);

    const int tid  = threadIdx.x;
    const int wId  = tid >> 5;
    const int lane = tid & 31;
    const int wRow = wId >> 2;
    const int wCol = wId & 3;
    const int rowN = blockIdx.x * MTILE;

    // load Wbot panel (Wg1 rows 128..255) fp16 -> smem
#pragma unroll
    for (int it = 0; it < 8; ++it) {
        const int i  = tid + it * NTHREADS;
        const int k  = i >> 4;
        const int c8 = (i & 15) * 8;
        *(uint4*)&Wp[k * WP_LD + c8] = *(const uint4*)&g_Wgh[(size_t)(128 + k) * JDIM + c8];
    }

    // gather: warp w computes rows w*8 .. w*8+7 of the E tile
    {
        const int c  = lane * 4;
        const float b0 = bg[c], b1 = bg[c + 1], b2 = bg[c + 2], b3 = bg[c + 3];
#pragma unroll
        for (int rr0 = 0; rr0 < 8; ++rr0) {
            const int rr = wId * 8 + rr0;
            const int g2 = rowN + rr;
            float4 e = make_float4(0.f, 0.f, 0.f, 0.f);
            if (g2 < M) {
                float4 acc = make_float4(0.f, 0.f, 0.f, 0.f);
#pragma unroll
                for (int s = 0; s < SSAMP; ++s) {
                    const int i0 = idx0[s * L_NODES + g2];
                    const int i1 = idx1[s * L_NODES + g2];
                    const uint2 au = *(const uint2*)&ABh[(size_t)i0 * 256 + c];
                    const uint2 bu = *(const uint2*)&ABh[(size_t)i1 * 256 + 128 + c];
                    const float2 a01 = __half22float2(*(const __half2*)&au.x);
                    const float2 a23 = __half22float2(*(const __half2*)&au.y);
                    const float2 b01 = __half22float2(*(const __half2*)&bu.x);
                    const float2 b23 = __half22float2(*(const __half2*)&bu.y);
                    acc.x += fmaxf(a01.x + b01.x + b0, 0.f);
                    acc.y += fmaxf(a01.y + b01.y + b1, 0.f);
                    acc.z += fmaxf(a23.x + b23.x + b2, 0.f);
                    acc.w += fmaxf(a23.y + b23.y + b3, 0.f);
                }
                const float inv = 1.f / (float)SSAMP;
                e.x = fmaxf(acc.x * inv, 0.f);
                e.y = fmaxf(acc.y * inv, 0.f);
                e.z = fmaxf(acc.z * inv, 0.f);
                e.w = fmaxf(acc.w * inv, 0.f);
            }
            sts_half4(&Eh[rr * HS_LD + c], e);
        }
    }
    __syncthreads();

    // GEMM: C = E(64x128) @ Wbot(128x128), all operands in smem
    wmma::fragment<wmma::accumulator, 16, 16, 16, float> c[2][2];
#pragma unroll
    for (int mi = 0; mi < 2; ++mi)
#pragma unroll
        for (int ni = 0; ni < 2; ++ni) wmma::fill_fragment(c[mi][ni], 0.f);
#pragma unroll
    for (int kc = 0; kc < 4; ++kc)
        mma_chunk32(&Eh[kc * 32], &Wp[(kc * 32) * WP_LD], HS_LD, WP_LD, c, wRow, wCol);
    __syncthreads();  // Wp reads done -> Cs may overwrite

#pragma unroll
    for (int mi = 0; mi < 2; ++mi)
#pragma unroll
        for (int ni = 0; ni < 2; ++ni)
            wmma::store_matrix_sync(&Cs[(wRow * 32 + mi * 16) * CS_LD + wCol * 32 + ni * 16],
                                    c[mi][ni], CS_LD, wmma::mem_row_major);
    __syncthreads();

    // epilogue: 4 threads/row (64 rows), each covers 32 features
    const int r  = tid >> 2;
    const int q  = tid & 3;
    const int f0 = q * 32;
    const int g2 = rowN + r;
    float s0 = 0.f, s1 = 0.f;
    if (g2 < M) {
#pragma unroll
        for (int j = 0; j < 8; ++j) {
            const int f = f0 + j * 4;
            const float4 cv = *(float4*)&Cs[r * CS_LD + f];
            const uint2 au = *(const uint2*)&ABh[(size_t)g2 * 256 + f];  // A = H@Wtop
            const float2 a01 = __half22float2(*(const __half2*)&au.x);
            const float2 a23 = __half22float2(*(const __half2*)&au.y);
            const float e0 = fmaxf(a01.x + cv.x + bg[f + 0], 0.f);
            const float e1 = fmaxf(a01.y + cv.y + bg[f + 1], 0.f);
            const float e2 = fmaxf(a23.x + cv.z + bg[f + 2], 0.f);
            const float e3 = fmaxf(a23.y + cv.w + bg[f + 3], 0.f);
            s0 += e0 * Wf[(f + 0) * 2] + e1 * Wf[(f + 1) * 2]
                + e2 * Wf[(f + 2) * 2] + e3 * Wf[(f + 3) * 2];
            s1 += e0 * Wf[(f + 0) * 2 + 1] + e1 * Wf[(f + 1) * 2 + 1]
                + e2 * Wf[(f + 2) * 2 + 1] + e3 * Wf[(f + 3) * 2 + 1];
        }
    }
#pragma unroll
    for (int off = 1; off <= 2; off <<= 1) {
        s0 += __shfl_xor_sync(0xffffffffu, s0, off);
        s1 += __shfl_xor_sync(0xffffffffu, s1, off);
    }
    if (q == 0 && g2 < M) {
        out[(size_t)g2 * 2 + 0] = s0 + bf[0];
        out[(size_t)g2 * 2 + 1] = s1 + bf[1];
    }
}

// ---------------------------------------------------------------------------
extern "C" void kernel_launch(void* const* d_in, const int* in_sizes, int n_in,
                              void* d_out, int out_size)
{
    const float* X    = (const float*)d_in[0];
    const float* Wh1  = (const float*)d_in[1];
    const float* bh1  = (const float*)d_in[2];
    const float* Wg1  = (const float*)d_in[3];
    const float* bg1  = (const float*)d_in[4];
    const float* Wf   = (const float*)d_in[5];
    const float* bf   = (const float*)d_in[6];
    const int*   idx0 = (const int*)d_in[7];
    const int*   idx1 = (const int*)d_in[8];
    float* out = (float*)d_out;

    __half* ABh;
    cudaGetSymbolAddress((void**)&ABh, g_ABh);

    cudaFuncSetAttribute(fused12, cudaFuncAttributeMaxDynamicSharedMemorySize, SMEM_TOTAL);
    cudaFuncSetAttribute(final_fused, cudaFuncAttributeMaxDynamicSharedMemorySize, SMEM_TOTAL);

    const int mtiles = (L_NODES + MTILE - 1) / MTILE;   // 1563

    // 0) weights -> fp16
    convert_w<<<128, 256>>>(Wh1, Wg1);

    // 1+2) ABh = fp16( relu(X@Wh1+bh1) @ [Wtop|Wbot] )
    fused12<<<mtiles, NTHREADS, SMEM_TOTAL>>>(X, bh1, ABh, L_NODES);

    // 3+4+5) gather -> E tile -> E@Wbot -> Wf epilogue
    final_fused<<<mtiles, NTHREADS, SMEM_TOTAL>>>(
        idx0, idx1, bg1, Wf, bf, ABh, out, L_NODES);
}